// round 15
// baseline (speedup 1.0000x reference)
#include <cuda_runtime.h>

// out[b,t,d] = x[b,t,d] * (sum_{k<t} x[b,k,d])
// B=8, T=4096, D=1024, fp32.
// Single-pass with decoupled lookback: each CTA handles one 512-t x 16-d tile
// (register-staged, float2), publishes its per-d block totals to global
// scratch, and sums predecessor aggregates to get its carry-in. One load
// burst -> one scan -> one emit per CTA (no multi-stage barrier convoy).
// Scratch flags self-reset each launch -> CUDA-graph replay safe.

#define T_DIM   4096
#define D_DIM   1024
#define VLANES  8                        // float2 lanes
#define D_TILE  16                       // d per column
#define SLICES  32
#define CHUNK   16                       // t-steps per thread
#define BLK_T   (SLICES * CHUNK)         // 512
#define NPOS    (T_DIM / BLK_T)          // 8 t-blocks per column
#define NCOL    512                      // 8 b * 64 d-tiles
#define NTHREADS (VLANES * SLICES)       // 256
#define ROW2    (D_DIM / 2)

// Cross-block scratch (module globals: zero-initialized at load, reset by the
// kernel itself at the end of every launch).
__device__ float g_agg[NPOS][NCOL][D_TILE];   // per-block totals per d
__device__ int   g_flag[NPOS][NCOL];          // == 16 when agg fully published
__device__ int   g_done[NCOL];                // lookback completions (pos 1..6)

__global__ __launch_bounds__(NTHREADS, 4)
void siso_scan_lookback(const float2* __restrict__ x, float2* __restrict__ out) {
    __shared__ float ssum[SLICES][D_TILE + 1];  // local exclusive prefixes
    __shared__ float lb[D_TILE];                // lookback carry per d

    const int tid    = threadIdx.x;
    const int lane_v = tid & (VLANES - 1);
    const int slice  = tid >> 3;
    const int wid    = tid >> 5;
    const int lid    = tid & 31;

    const int pos = blockIdx.x >> 9;            // t-block index (slow dim)
    const int col = blockIdx.x & (NCOL - 1);    // column = (b, d_tile)
    const int d_tile = col & 63;
    const int b      = col >> 6;

    const unsigned base = (unsigned)b * (T_DIM * ROW2)
                        + (unsigned)d_tile * VLANES + (unsigned)lane_v
                        + ((unsigned)pos * BLK_T + (unsigned)slice * CHUNK) * ROW2;
    const float2* __restrict__ p = x   + base;
    float2*       __restrict__ q = out + base;

    // ---- Load burst: 16 independent LDG.64, register-staged ----
    float2 v[CHUNK];
    float sx = 0.f, sy = 0.f;
    #pragma unroll
    for (int i = 0; i < CHUNK; ++i) {
        v[i] = p[(unsigned)i * ROW2];
        sx += v[i].x;
        sy += v[i].y;
    }
    ssum[slice][lane_v * 2]     = sx;
    ssum[slice][lane_v * 2 + 1] = sy;
    __syncthreads();

    // ---- Local scan: each warp shuffle-scans 2 d-columns; publish totals ----
    #pragma unroll
    for (int cc = 0; cc < 2; ++cc) {
        const int cd = wid * 2 + cc;
        float val  = ssum[lid][cd];
        float incl = val;
        #pragma unroll
        for (int off = 1; off < 32; off <<= 1) {
            float n = __shfl_up_sync(0xFFFFFFFFu, incl, off);
            if (lid >= off) incl += n;
        }
        ssum[lid][cd] = incl - val;             // pure-local exclusive prefix
        if (lid == 31 && pos < NPOS - 1) {      // publish block total (release)
            g_agg[pos][col][cd] = incl;
            __threadfence();
            atomicAdd(&g_flag[pos][col], 1);
        }
    }
    __syncthreads();

    // ---- Lookback (warp 0): sum predecessor aggregates ----
    if (wid == 0) {
        if (pos == 0) {
            if (lid < D_TILE) lb[lid] = 0.f;
        } else {
            // lanes 0..pos-1 each poll one predecessor flag
            bool ready = (lid >= pos);
            unsigned nr;
            do {
                if (!ready) {
                    int f = *((volatile int*)&g_flag[lid][col]);
                    ready = (f >= 16);
                }
                nr = __ballot_sync(0xFFFFFFFFu, !ready);
            } while (nr != 0);
            __threadfence();                    // acquire
            if (lid < D_TILE) {
                float s = 0.f;
                for (int pp = 0; pp < pos; ++pp)
                    s += g_agg[pp][col][lid];
                lb[lid] = s;
            }
            __syncwarp();
            if (lid == 0 && pos <= NPOS - 2)    // pos 1..6: signal done reading
                atomicAdd(&g_done[col], 1);
        }
    }
    __syncthreads();

    // ---- Emit from registers ----
    float rx = ssum[slice][lane_v * 2]     + lb[lane_v * 2];
    float ry = ssum[slice][lane_v * 2 + 1] + lb[lane_v * 2 + 1];
    #pragma unroll
    for (int i = 0; i < CHUNK; ++i) {
        float2 o;
        o.x = v[i].x * rx;
        o.y = v[i].y * ry;
        q[(unsigned)i * ROW2] = o;
        rx += v[i].x;
        ry += v[i].y;
    }

    // ---- Cleanup (last block of each column): reset scratch for replay ----
    if (pos == NPOS - 1 && wid == 0) {
        if (lid == 0) {
            while (*((volatile int*)&g_done[col]) != NPOS - 2) { }
        }
        __syncwarp();
        if (lid < NPOS - 1) g_flag[lid][col] = 0;
        if (lid == 0)       g_done[col] = 0;
    }
}

extern "C" void kernel_launch(void* const* d_in, const int* in_sizes, int n_in,
                              void* d_out, int out_size) {
    const float2* x = (const float2*)d_in[0];
    float2* out = (float2*)d_out;

    const int n = in_sizes[0];                    // B*T*D
    const int B = n / (T_DIM * D_DIM);            // 8
    const int blocks = NPOS * B * (D_DIM / D_TILE);  // 8 * 512 = 4096

    siso_scan_lookback<<<blocks, NTHREADS>>>(x, out);
}

// round 17
// speedup vs baseline: 1.1557x; 1.1557x over previous
#include <cuda_runtime.h>

// out[b,t,d] = x[b,t,d] * (sum_{k<t} x[b,k,d])
// B=8, T=4096, D=1024, fp32.
// R12 skeleton (best bench so far): single-pass, register-staged, float2,
// 256-thr blocks, CHUNK=16, 4 CTAs/SM for phase interleaving.
// Change: loads use __ldcs (L2 evict-first). Read lines are single-use, so
// deprioritizing them leaves more L2 for dirty output lines, deferring write
// drain past the timed region and reducing in-kernel DRAM traffic.

#define T_DIM   4096
#define D_DIM   1024
#define VLANES  8                        // float2 lanes per slice-row
#define D_TILE  (VLANES * 2)             // 16 d per block
#define SLICES  32
#define CHUNK   16                       // t-steps per thread per stage
#define STAGE_T (SLICES * CHUNK)         // 512
#define NSTAGE  (T_DIM / STAGE_T)        // 8
#define NTHREADS (VLANES * SLICES)       // 256
#define ROW2    (D_DIM / 2)              // row stride in float2 units

__global__ __launch_bounds__(NTHREADS, 4)
void siso_scan_v2cs(const float2* __restrict__ x, float2* __restrict__ out) {
    __shared__ float ssum[SLICES][D_TILE + 1];  // [slice][d], stride 17
    __shared__ float carry[D_TILE];             // running prefix per d

    const int tid    = threadIdx.x;
    const int lane_v = tid & (VLANES - 1);      // float2 lane (0..7)
    const int slice  = tid >> 3;                // t-slice (0..31)
    const int wid    = tid >> 5;                // warp id (0..7)
    const int lid    = tid & 31;

    const int d_tiles = D_DIM / D_TILE;         // 64
    const int d_tile  = blockIdx.x & (d_tiles - 1);
    const int b       = blockIdx.x >> 6;

    // base in float2 units
    const unsigned base = (unsigned)b * (T_DIM * ROW2)
                        + (unsigned)d_tile * VLANES + (unsigned)lane_v;

    if (tid < D_TILE) carry[tid] = 0.f;
    __syncthreads();

    for (int st = 0; st < NSTAGE; ++st) {
        const unsigned t_base = (unsigned)st * STAGE_T + (unsigned)slice * CHUNK;
        const float2* __restrict__ p = x   + base + t_base * ROW2;
        float2*       __restrict__ q = out + base + t_base * ROW2;

        // Load chunk into registers (16 independent streaming LDG.64).
        float2 v[CHUNK];
        float sx = 0.f, sy = 0.f;
        #pragma unroll
        for (int i = 0; i < CHUNK; ++i) {
            v[i] = __ldcs(&p[(unsigned)i * ROW2]);
            sx += v[i].x;
            sy += v[i].y;
        }
        ssum[slice][lane_v * 2]     = sx;
        ssum[slice][lane_v * 2 + 1] = sy;
        __syncthreads();

        // Each warp shuffle-scans 2 d-columns (32 slice sums each).
        // stride-17 smem -> conflict-free.
        #pragma unroll
        for (int cc = 0; cc < 2; ++cc) {
            const int col = wid * 2 + cc;
            float val  = ssum[lid][col];
            float incl = val;
            #pragma unroll
            for (int off = 1; off < 32; off <<= 1) {
                float n = __shfl_up_sync(0xFFFFFFFFu, incl, off);
                if (lid >= off) incl += n;
            }
            float c = carry[col];
            ssum[lid][col] = (incl - val) + c;       // exclusive + carry-in
            if (lid == 31) carry[col] = incl + c;    // carry-out
        }
        __syncthreads();

        // Emit from registers (16 STG.64); next stage's loads overlap drain.
        float rx = ssum[slice][lane_v * 2];
        float ry = ssum[slice][lane_v * 2 + 1];
        #pragma unroll
        for (int i = 0; i < CHUNK; ++i) {
            float2 o;
            o.x = v[i].x * rx;
            o.y = v[i].y * ry;
            q[(unsigned)i * ROW2] = o;
            rx += v[i].x;
            ry += v[i].y;
        }
        // ssum/carry only rewritten after the next in-loop __syncthreads().
    }
}

extern "C" void kernel_launch(void* const* d_in, const int* in_sizes, int n_in,
                              void* d_out, int out_size) {
    const float2* x = (const float2*)d_in[0];
    float2* out = (float2*)d_out;

    const int n = in_sizes[0];                    // B*T*D
    const int B = n / (T_DIM * D_DIM);            // 8
    const int blocks = B * (D_DIM / D_TILE);      // 512

    siso_scan_v2cs<<<blocks, NTHREADS>>>(x, out);
}